// round 1
// baseline (speedup 1.0000x reference)
#include <cuda_runtime.h>
#include <math.h>

#define Bn 64
#define Sn 512
#define Hn 768
#define Tn 9
#define NCHUNK 8
#define CHUNK (Sn / NCHUNK) /* 64 */

// ---- scratch (static device memory; no allocations allowed) ----
__device__ float d_em[Bn * Sn * Tn];          // emissions, [b][s][t]
__device__ float d_CM[Bn * NCHUNK * 81];      // chunk transfer matrices M[i][j]
__device__ int   d_CE[Bn * NCHUNK];           // chunk log2-scale (exact int exponents)
__device__ float d_nll[Bn];

// ============================================================
// Kernel A: emissions[b,s,t] = relu(emb[b,s,:] . W[t,:] + b[t])
// Warp handles 4 rows; lane = (q=lane/8 row, r=lane&7 k-slice).
// W staged in shared as float4; emb read as coalesced float4.
// ============================================================
__global__ __launch_bounds__(256) void emis_kernel(
    const float* __restrict__ emb,
    const float* __restrict__ W,
    const float* __restrict__ bias)
{
    __shared__ float4 Wsm[Tn * 192];   // 9 x 768 floats = 27648 B
    __shared__ float  bsm[Tn];

    int tid = threadIdx.x;
    const float4* Wg = (const float4*)W;
    for (int i = tid; i < Tn * 192; i += 256) Wsm[i] = Wg[i];
    if (tid < Tn) bsm[tid] = bias[tid];
    __syncthreads();

    int warp = tid >> 5, lane = tid & 31;
    int q = lane >> 3, r = lane & 7;
    int row = blockIdx.x * 32 + warp * 4 + q;   // 1024 blocks * 32 rows = 32768

    const float4* e4p = (const float4*)emb + (size_t)row * 192;

    float acc[Tn];
#pragma unroll
    for (int t = 0; t < Tn; t++) acc[t] = 0.f;

#pragma unroll
    for (int jj = 0; jj < 24; jj++) {
        int k4 = r + 8 * jj;
        float4 e = e4p[k4];
#pragma unroll
        for (int t = 0; t < Tn; t++) {
            float4 w = Wsm[t * 192 + k4];
            acc[t] = fmaf(e.x, w.x, acc[t]);
            acc[t] = fmaf(e.y, w.y, acc[t]);
            acc[t] = fmaf(e.z, w.z, acc[t]);
            acc[t] = fmaf(e.w, w.w, acc[t]);
        }
    }
    // reduce over the 8 k-slices (lanes r=0..7 within each quad)
#pragma unroll
    for (int t = 0; t < Tn; t++) {
        acc[t] += __shfl_xor_sync(0xffffffffu, acc[t], 4);
        acc[t] += __shfl_xor_sync(0xffffffffu, acc[t], 2);
        acc[t] += __shfl_xor_sync(0xffffffffu, acc[t], 1);
    }
    if (r == 0) {
#pragma unroll
        for (int t = 0; t < Tn; t++) {
            float v = acc[t] + bsm[t];
            d_em[(size_t)row * Tn + t] = v > 0.f ? v : 0.f;
        }
    }
}

// ============================================================
// Kernel B: per (batch, chunk) 9x9 transfer matrix in linear
// space with exact power-of-2 rescaling.
//   Step matrix: Step[k][j] = exp(trans[k][j]) * exp(em[t][j])
//   M <- M @ Step  (masked steps skipped == identity)
// Lane L<27: j = L/3 (output column), g = L%3 (3 rows: 3g..3g+2)
// ============================================================
__global__ __launch_bounds__(32) void chunk_kernel(
    const int* __restrict__ labels,
    const int* __restrict__ mask,
    const float* __restrict__ trans)
{
    int b = blockIdx.x >> 3;
    int c = blockIdx.x & 7;
    int lane = threadIdx.x;
    int j = lane / 3, g = lane % 3;
    bool act = lane < 27;

    __shared__ float Mb[2][81];

    float eT[9];
    if (act) {
#pragma unroll
        for (int k = 0; k < 9; k++) eT[k] = __expf(trans[k * 9 + j]);
#pragma unroll
        for (int ii = 0; ii < 3; ii++) {
            int i = 3 * g + ii;
            Mb[0][i * 9 + j] = (i == j) ? 1.f : 0.f;
        }
    }
    __syncwarp();

    int cur = 0;
    int esum = 0, cnt = 0;
    int t0 = (c == 0) ? 1 : c * CHUNK;
    int t1 = (c + 1) * CHUNK;

    for (int t = t0; t < t1; t++) {
        int lab = labels[b * Sn + t];
        bool mb = (mask[b * Sn + t] != 0) && (lab != -100);   // warp-uniform
        if (!mb) continue;

        float v0 = 0.f, v1 = 0.f, v2 = 0.f;
        if (act) {
            float p = __expf(d_em[(b * Sn + t) * Tn + j]);
            const float* Mc = Mb[cur];
            float s0 = 0.f, s1 = 0.f, s2 = 0.f;
#pragma unroll
            for (int k = 0; k < 9; k++) {
                float ek = eT[k];
                s0 = fmaf(Mc[(3 * g + 0) * 9 + k], ek, s0);
                s1 = fmaf(Mc[(3 * g + 1) * 9 + k], ek, s1);
                s2 = fmaf(Mc[(3 * g + 2) * 9 + k], ek, s2);
            }
            v0 = s0 * p; v1 = s1 * p; v2 = s2 * p;
        }
        __syncwarp();
        if (act) {
            float* Mn = Mb[cur ^ 1];
            Mn[(3 * g + 0) * 9 + j] = v0;
            Mn[(3 * g + 1) * 9 + j] = v1;
            Mn[(3 * g + 2) * 9 + j] = v2;
        }
        cur ^= 1;
        __syncwarp();

        if (++cnt == 4) {           // renorm every 4 active steps
            cnt = 0;
            float lm = act ? fmaxf(v0, fmaxf(v1, v2)) : 0.f;
#pragma unroll
            for (int o = 16; o > 0; o >>= 1)
                lm = fmaxf(lm, __shfl_xor_sync(0xffffffffu, lm, o));
            int e = ilogbf(lm);
            if (e != 0) {
                float sc = exp2f((float)(-e));   // exact power of 2
                if (act) {
                    float* M = Mb[cur];
                    M[(3 * g + 0) * 9 + j] = v0 * sc;
                    M[(3 * g + 1) * 9 + j] = v1 * sc;
                    M[(3 * g + 2) * 9 + j] = v2 * sc;
                }
                esum += e;
                __syncwarp();
            }
        }
    }

    if (act) {
        const float* M = Mb[cur];
#pragma unroll
        for (int ii = 0; ii < 3; ii++) {
            int i = 3 * g + ii;
            d_CM[(b * NCHUNK + c) * 81 + i * 9 + j] = M[i * 9 + j];
        }
    }
    if (lane == 0) d_CE[b * NCHUNK + c] = esum;
}

// ============================================================
// Kernel C: per-batch — numerator score + combine chunk matrices
// into the denominator. One warp per batch.
// ============================================================
__global__ __launch_bounds__(32) void combine_kernel(
    const int* __restrict__ labels,
    const int* __restrict__ mask,
    const float* __restrict__ trans,
    const float* __restrict__ startt,
    const float* __restrict__ endt)
{
    int b = blockIdx.x;
    int lane = threadIdx.x;

    // ---- numerator partial sums (all 32 lanes, strided over t) ----
    float ps = 0.f;
    int cntm = 0;
    for (int t = lane; t < Sn; t += 32) {
        int lab = labels[b * Sn + t];
        bool valid = lab != -100;
        int lm = valid ? lab : 0;
        bool mb = (mask[b * Sn + t] != 0) && valid;
        if (mb) cntm++;
        if (mb && t >= 1) {
            int labp = labels[b * Sn + t - 1];
            int lmp = (labp != -100) ? labp : 0;
            ps += d_em[(b * Sn + t) * Tn + lm] + trans[lmp * 9 + lm];
        }
    }
#pragma unroll
    for (int o = 16; o > 0; o >>= 1) {
        ps += __shfl_xor_sync(0xffffffffu, ps, o);
        cntm += __shfl_xor_sync(0xffffffffu, cntm, o);
    }

    // ---- denominator: alpha0 through 8 chunk matrices (linear + log2 scale) ----
    int j = lane;
    float a = 0.f;
    if (j < 9) a = __expf(startt[j] + d_em[(b * Sn + 0) * Tn + j]);
    int esum = 0;

    for (int c = 0; c < NCHUNK; c++) {
        float Mi[9];
#pragma unroll
        for (int i = 0; i < 9; i++)
            Mi[i] = (j < 9) ? d_CM[(b * NCHUNK + c) * 81 + i * 9 + j] : 0.f;
        float s = 0.f;
#pragma unroll
        for (int i = 0; i < 9; i++)
            s = fmaf(__shfl_sync(0xffffffffu, a, i), Mi[i], s);
        a = (j < 9) ? s : 0.f;
        esum += d_CE[b * NCHUNK + c];

        float lm = a;
#pragma unroll
        for (int o = 16; o > 0; o >>= 1)
            lm = fmaxf(lm, __shfl_xor_sync(0xffffffffu, lm, o));
        int e = ilogbf(lm);
        if (e != 0) { a *= exp2f((float)(-e)); esum += e; }
    }

    float v = (j < 9) ? a * __expf(endt[j]) : 0.f;
#pragma unroll
    for (int o = 16; o > 0; o >>= 1)
        v += __shfl_xor_sync(0xffffffffu, v, o);

    if (lane == 0) {
        float denom = (float)esum * 0.69314718055994530942f + __logf(v);
        int l0 = labels[b * Sn];
        if (l0 == -100) l0 = 0;
        float first = startt[l0] + d_em[(b * Sn + 0) * Tn + l0];
        int last_idx = cntm - 1;                    // lengths >= 1 so cntm >= 1
        int ll = labels[b * Sn + last_idx];
        if (ll == -100) ll = 0;
        float num = first + ps + endt[ll];
        d_nll[b] = denom - num;
    }
}

// ============================================================
// Kernel D: mean over batch -> scalar output
// ============================================================
__global__ void final_kernel(float* __restrict__ out)
{
    __shared__ float s[64];
    int t = threadIdx.x;
    s[t] = d_nll[t];
    __syncthreads();
    for (int o = 32; o > 0; o >>= 1) {
        if (t < o) s[t] += s[t + o];
        __syncthreads();
    }
    if (t == 0) out[0] = s[0] * (1.0f / 64.0f);
}

// ============================================================
extern "C" void kernel_launch(void* const* d_in, const int* in_sizes, int n_in,
                              void* d_out, int out_size)
{
    const float* emb    = (const float*)d_in[0];
    const float* W      = (const float*)d_in[1];
    const float* bias   = (const float*)d_in[2];
    const float* startt = (const float*)d_in[3];
    const float* trans  = (const float*)d_in[4];
    const float* endt   = (const float*)d_in[5];
    const int*   labels = (const int*)d_in[6];
    const int*   mask   = (const int*)d_in[7];

    emis_kernel<<<1024, 256>>>(emb, W, bias);
    chunk_kernel<<<Bn * NCHUNK, 32>>>(labels, mask, trans);
    combine_kernel<<<Bn, 32>>>(labels, mask, trans, startt, endt);
    final_kernel<<<1, 64>>>((float*)d_out);
}

// round 3
// speedup vs baseline: 1.1509x; 1.1509x over previous
#include <cuda_runtime.h>
#include <math.h>

#define Bn 64
#define Sn 512
#define Hn 768
#define Tn 9
#define NCHUNK 16
#define CHUNK 32           /* Sn / NCHUNK */
#define KT 32              /* k-tile for emissions GEMM (smem budget) */

// ---- static device scratch (no allocations allowed) ----
__device__ float d_em[Bn * Sn * Tn];       // relu emissions
__device__ float d_ep[Bn * Sn * Tn];       // exp(relu emissions)
__device__ float d_CM[Bn * NCHUNK * 81];   // chunk transfer matrices
__device__ int   d_CE[Bn * NCHUNK];        // chunk log2 scales
__device__ unsigned d_bcnt[Bn];            // per-batch chunk-done tickets (zero-init)
__device__ float d_sum;                    // final accumulator (zero-init)
__device__ unsigned d_cnt;                 // batch-done ticket (zero-init)

// ============================================================
// Kernel A: emissions = relu(emb @ W^T + b), store em and exp(em).
// Block = 128 threads = 128 rows (one row per thread).
// emb tile transposed through smem (coalesced LDG -> conflict-free LDS),
// W read from smem as warp-uniform float4 BROADCASTS (1 wavefront each).
// Static smem: 27648 (W) + 16512 (E) = 44160 B < 48 KB.
// ============================================================
__global__ __launch_bounds__(128) void emis_kernel(
    const float* __restrict__ emb,
    const float* __restrict__ W,
    const float* __restrict__ bias)
{
    __shared__ float Wsm[Tn * Hn];       // 27648 B
    __shared__ float Esm[KT * 129];      // 16512 B  (k-major, pad 129)

    int tid = threadIdx.x;

    // stage W (1728 float4)
    {
        const float4* Wg = (const float4*)W;
        float4* Ws4 = (float4*)Wsm;
        for (int i = tid; i < Tn * Hn / 4; i += 128) Ws4[i] = Wg[i];
    }

    float bv[Tn];
#pragma unroll
    for (int t = 0; t < Tn; t++) bv[t] = __ldg(bias + t);

    int row0 = blockIdx.x * 128;
    const float4* eg = (const float4*)emb + (size_t)row0 * (Hn / 4);

    float acc[Tn];
#pragma unroll
    for (int t = 0; t < Tn; t++) acc[t] = 0.f;

    int f = tid & 7;         // float4 index within 32-wide k tile
    int rsub = tid >> 3;     // row sub-offset 0..15

#pragma unroll 1
    for (int kt = 0; kt < Hn / KT; kt++) {
        __syncthreads();     // protect Esm reuse
        // load tile: 128 rows x 32 k, coalesced, transpose into Esm[k][row]
#pragma unroll
        for (int p = 0; p < 8; p++) {
            int r = rsub + 16 * p;
            float4 v = eg[(size_t)r * (Hn / 4) + kt * (KT / 4) + f];
            int kk = f * 4;
            Esm[(kk + 0) * 129 + r] = v.x;
            Esm[(kk + 1) * 129 + r] = v.y;
            Esm[(kk + 2) * 129 + r] = v.z;
            Esm[(kk + 3) * 129 + r] = v.w;
        }
        __syncthreads();

        const float* Wk = Wsm + kt * KT;
#pragma unroll
        for (int kk = 0; kk < KT; kk += 4) {
            float e0 = Esm[(kk + 0) * 129 + tid];
            float e1 = Esm[(kk + 1) * 129 + tid];
            float e2 = Esm[(kk + 2) * 129 + tid];
            float e3 = Esm[(kk + 3) * 129 + tid];
#pragma unroll
            for (int t = 0; t < Tn; t++) {
                float4 w = *(const float4*)(Wk + t * Hn + kk);  // broadcast
                acc[t] = fmaf(e0, w.x, acc[t]);
                acc[t] = fmaf(e1, w.y, acc[t]);
                acc[t] = fmaf(e2, w.z, acc[t]);
                acc[t] = fmaf(e3, w.w, acc[t]);
            }
        }
    }

    size_t base = (size_t)(row0 + tid) * Tn;
#pragma unroll
    for (int t = 0; t < Tn; t++) {
        float v = acc[t] + bv[t];
        v = v > 0.f ? v : 0.f;
        d_em[base + t] = v;
        d_ep[base + t] = __expf(v);
    }
}

// ============================================================
// Kernel B: per (batch, chunk) 9x9 transfer matrix, pure shuffles,
// linear space with exact power-of-2 rescaling. Last chunk of each
// batch also runs the per-batch combine + numerator; the 64th batch
// writes the final mean and resets the tickets for graph replay.
// Lane layout: lane = 3j + g holds M[3g+ii][j], ii=0..2 (27 active).
// ============================================================
__global__ __launch_bounds__(32) void chunk_kernel(
    const int* __restrict__ labels,
    const int* __restrict__ mask,
    const float* __restrict__ trans,
    const float* __restrict__ startt,
    const float* __restrict__ endt,
    float* __restrict__ out)
{
    int blk = blockIdx.x;
    int b = blk >> 4;
    int c = blk & 15;
    int lane = threadIdx.x;
    int j = lane / 3, g = lane - 3 * j;
    bool act = lane < 27;
    int jc = act ? j : 8;

    __shared__ float Psm[CHUNK * Tn];

    // per-step active bitmask (warp-uniform ballot)
    int base = b * Sn + c * CHUNK;
    {
        int lab = labels[base + lane];
        int mk  = mask[base + lane];
        unsigned bit = (mk != 0 && lab != -100) ? 1u : 0u;
        unsigned bits = __ballot_sync(0xffffffffu, bit);
        if (c == 0) bits &= ~1u;

        // load exp(emissions) for the chunk into smem (coalesced)
        const float* ep = d_ep + (size_t)base * Tn;
        for (int i = lane; i < CHUNK * Tn; i += 32) Psm[i] = ep[i];

        float eT[Tn];
#pragma unroll
        for (int k = 0; k < Tn; k++)
            eT[k] = act ? __expf(__ldg(trans + k * Tn + jc)) : 0.f;

        __syncwarp();

        // v = identity columns of M
        float v0 = (act && 3 * g + 0 == j) ? 1.f : 0.f;
        float v1 = (act && 3 * g + 1 == j) ? 1.f : 0.f;
        float v2 = (act && 3 * g + 2 == j) ? 1.f : 0.f;
        int esum = 0, cnt = 0;

        for (int s = 0; s < CHUNK; s++) {
            if (!((bits >> s) & 1u)) continue;
            float p = Psm[s * Tn + jc];
            float n0 = 0.f, n1 = 0.f, n2 = 0.f;
#pragma unroll
            for (int k = 0; k < Tn; k++) {
                int src = 3 * k + g;
                float a0 = __shfl_sync(0xffffffffu, v0, src);
                float a1 = __shfl_sync(0xffffffffu, v1, src);
                float a2 = __shfl_sync(0xffffffffu, v2, src);
                n0 = fmaf(a0, eT[k], n0);
                n1 = fmaf(a1, eT[k], n1);
                n2 = fmaf(a2, eT[k], n2);
            }
            v0 = n0 * p; v1 = n1 * p; v2 = n2 * p;

            if (++cnt == 4) {     // exact power-of-2 renorm
                cnt = 0;
                float lm = fmaxf(v0, fmaxf(v1, v2));
#pragma unroll
                for (int o = 16; o > 0; o >>= 1)
                    lm = fmaxf(lm, __shfl_xor_sync(0xffffffffu, lm, o));
                int e = ilogbf(lm);
                if (e != 0) {
                    float sc = exp2f((float)(-e));
                    v0 *= sc; v1 *= sc; v2 *= sc;
                    esum += e;
                }
            }
        }

        if (act) {
            float* M = d_CM + (size_t)blk * 81;
            M[(3 * g + 0) * 9 + j] = v0;
            M[(3 * g + 1) * 9 + j] = v1;
            M[(3 * g + 2) * 9 + j] = v2;
        }
        if (lane == 0) d_CE[blk] = esum;
    }

    // ---- per-batch combine: last chunk block of batch b does it ----
    __threadfence();
    unsigned done = 0;
    if (lane == 0) done = (atomicAdd(&d_bcnt[b], 1u) == NCHUNK - 1) ? 1u : 0u;
    done = __shfl_sync(0xffffffffu, done, 0);
    if (!done) return;

    // numerator partial sums (strided over t)
    float ps = 0.f;
    int cntm = 0;
    for (int t = lane; t < Sn; t += 32) {
        int lab2 = labels[b * Sn + t];
        bool valid = lab2 != -100;
        int lm = valid ? lab2 : 0;
        bool mb = (mask[b * Sn + t] != 0) && valid;
        if (mb) cntm++;
        if (mb && t >= 1) {
            int labp = labels[b * Sn + t - 1];
            int lmp = (labp != -100) ? labp : 0;
            ps += d_em[(size_t)(b * Sn + t) * Tn + lm] + __ldg(trans + lmp * Tn + lm);
        }
    }
#pragma unroll
    for (int o = 16; o > 0; o >>= 1) {
        ps += __shfl_xor_sync(0xffffffffu, ps, o);
        cntm += __shfl_xor_sync(0xffffffffu, cntm, o);
    }

    // denominator: alpha0 through 16 chunk matrices
    int jj = lane;
    int jx = jj < 9 ? jj : 0;
    float a = (jj < 9) ? __expf(__ldg(startt + jx)) * d_ep[(size_t)(b * Sn) * Tn + jx] : 0.f;
    int es2 = 0;

#pragma unroll 2
    for (int c2 = 0; c2 < NCHUNK; c2++) {
        const float* M = d_CM + (size_t)(b * NCHUNK + c2) * 81;
        float Mi[9];
#pragma unroll
        for (int i = 0; i < 9; i++) Mi[i] = M[i * 9 + jx];
        float s = 0.f;
#pragma unroll
        for (int i = 0; i < 9; i++)
            s = fmaf(__shfl_sync(0xffffffffu, a, i), Mi[i], s);
        a = (jj < 9) ? s : 0.f;
        es2 += d_CE[b * NCHUNK + c2];

        float lm = a;
#pragma unroll
        for (int o = 16; o > 0; o >>= 1)
            lm = fmaxf(lm, __shfl_xor_sync(0xffffffffu, lm, o));
        int e = ilogbf(lm);
        if (e != 0) { a *= exp2f((float)(-e)); es2 += e; }
    }

    float v = (jj < 9) ? a * __expf(__ldg(endt + jx)) : 0.f;
#pragma unroll
    for (int o = 16; o > 0; o >>= 1)
        v += __shfl_xor_sync(0xffffffffu, v, o);

    if (lane == 0) {
        float denom = (float)es2 * 0.69314718055994530942f + __logf(v);
        int l0 = labels[b * Sn];
        if (l0 == -100) l0 = 0;
        float first = __ldg(startt + l0) + d_em[(size_t)(b * Sn) * Tn + l0];
        int last_idx = cntm - 1;
        int ll = labels[b * Sn + last_idx];
        if (ll == -100) ll = 0;
        float num = first + ps + __ldg(endt + ll);
        float nll = denom - num;

        // reset per-batch ticket for next graph replay
        d_bcnt[b] = 0;

        // global finalize: 64th batch writes the mean and resets
        atomicAdd(&d_sum, nll * (1.0f / (float)Bn));
        __threadfence();
        unsigned cdone = atomicAdd(&d_cnt, 1u);
        if (cdone == Bn - 1) {
            float tot = atomicAdd(&d_sum, 0.0f);  // coherent read
            out[0] = tot;
            atomicExch(&d_sum, 0.0f);
            atomicExch(&d_cnt, 0u);
        }
    }
}

// ============================================================
extern "C" void kernel_launch(void* const* d_in, const int* in_sizes, int n_in,
                              void* d_out, int out_size)
{
    const float* emb    = (const float*)d_in[0];
    const float* W      = (const float*)d_in[1];
    const float* bias   = (const float*)d_in[2];
    const float* startt = (const float*)d_in[3];
    const float* trans  = (const float*)d_in[4];
    const float* endt   = (const float*)d_in[5];
    const int*   labels = (const int*)d_in[6];
    const int*   mask   = (const int*)d_in[7];

    emis_kernel<<<256, 128>>>(emb, W, bias);
    chunk_kernel<<<Bn * NCHUNK, 32>>>(labels, mask, trans, startt, endt,
                                      (float*)d_out);
}

// round 4
// speedup vs baseline: 1.1632x; 1.0107x over previous
#include <cuda_runtime.h>
#include <math.h>

#define Bn 64
#define Sn 512
#define Hn 768
#define Tn 9
#define NCHUNK 32
#define CHUNK 16           /* Sn / NCHUNK */

// ---- static device scratch (no allocations allowed) ----
__device__ float d_em[Bn * Sn * Tn];       // relu emissions
__device__ float d_ep[Bn * Sn * Tn];       // exp(relu emissions)
__device__ float d_CM[Bn * NCHUNK * 81];   // chunk transfer matrices
__device__ int   d_CE[Bn * NCHUNK];        // chunk log2 scales
__device__ unsigned d_bcnt[Bn];            // per-batch chunk tickets (zero-init)
__device__ float d_sum;                    // final accumulator (zero-init)
__device__ unsigned d_cnt;                 // batch ticket (zero-init)

// ============================================================
// Kernel A: emissions = relu(emb @ W^T + b); store em and exp(em).
// No smem, no __syncthreads. Warp = 8 rows x 4 lanes (k-split).
// W is L1-resident (27KB) and deduped across the 8 row-groups.
// emb reads: 4 lanes x 16B = 64B contiguous per row-segment.
// ============================================================
__global__ __launch_bounds__(256) void emis_kernel(
    const float* __restrict__ emb,
    const float* __restrict__ W,
    const float* __restrict__ bias)
{
    int tid  = threadIdx.x;
    int lane = tid & 31;
    int warp = tid >> 5;
    int rsub = lane >> 2;          // 0..7  (row within warp)
    int q    = lane & 3;           // 0..3  (k-slice)
    int row  = blockIdx.x * 64 + warp * 8 + rsub;

    const float4* eg = (const float4*)emb + (size_t)row * (Hn / 4);
    const float4* Wg = (const float4*)W;

    float acc[Tn];
#pragma unroll
    for (int t = 0; t < Tn; t++) acc[t] = 0.f;

#pragma unroll 4
    for (int jj = 0; jj < Hn / 16; jj++) {   // 48 iters, lane k4 = q+4*jj
        int k4 = q + 4 * jj;
        float4 e = __ldg(eg + k4);
#pragma unroll
        for (int t = 0; t < Tn; t++) {
            float4 w = __ldg(Wg + t * (Hn / 4) + k4);
            acc[t] = fmaf(e.x, w.x, acc[t]);
            acc[t] = fmaf(e.y, w.y, acc[t]);
            acc[t] = fmaf(e.z, w.z, acc[t]);
            acc[t] = fmaf(e.w, w.w, acc[t]);
        }
    }

    // reduce over the 4 k-slices (q bits are the low 2 lane bits)
#pragma unroll
    for (int t = 0; t < Tn; t++) {
        acc[t] += __shfl_xor_sync(0xffffffffu, acc[t], 2);
        acc[t] += __shfl_xor_sync(0xffffffffu, acc[t], 1);
    }

    if (q == 0) {
        size_t base = (size_t)row * Tn;
#pragma unroll
        for (int t = 0; t < Tn; t++) {
            float v = acc[t] + __ldg(bias + t);
            v = v > 0.f ? v : 0.f;
            d_em[base + t] = v;
            d_ep[base + t] = __expf(v);
        }
    }
}

// ============================================================
// Kernel B: per (batch, chunk of 16) 9x9 transfer matrix.
// Branchless blended steps, REDUX renorm. Last block per batch
// stages all 32 matrices into smem and runs the combine chain;
// 64th batch writes the mean.
// Lane layout: lane = 3j+g holds M[3g+ii][j], ii=0..2 (27 active).
// ============================================================
__global__ __launch_bounds__(32) void chunk_kernel(
    const int* __restrict__ labels,
    const int* __restrict__ mask,
    const float* __restrict__ trans,
    const float* __restrict__ startt,
    const float* __restrict__ endt,
    float* __restrict__ out)
{
    int blk = blockIdx.x;
    int b = blk >> 5;
    int c = blk & 31;
    int lane = threadIdx.x;
    int j = lane / 3, g = lane - 3 * j;
    bool act = lane < 27;
    int jc = act ? j : 8;

    __shared__ float Psm[CHUNK * Tn];        // 576 B
    __shared__ float CMsm[NCHUNK * 81];      // 10368 B (combine only)

    int base = b * Sn + c * CHUNK;

    unsigned bit = 0;
    if (lane < CHUNK) {
        int lab = labels[base + lane];
        int mk  = mask[base + lane];
        bit = (mk != 0 && lab != -100) ? 1u : 0u;
    }
    unsigned bits = __ballot_sync(0xffffffffu, bit);
    if (c == 0) bits &= ~1u;

    const float* ep = d_ep + (size_t)base * Tn;
    for (int i = lane; i < CHUNK * Tn; i += 32) Psm[i] = ep[i];

    float eT[Tn];
#pragma unroll
    for (int k = 0; k < Tn; k++)
        eT[k] = __expf(__ldg(trans + k * Tn + jc));

    __syncwarp();

    float v0 = (act && 3 * g + 0 == j) ? 1.f : 0.f;
    float v1 = (act && 3 * g + 1 == j) ? 1.f : 0.f;
    float v2 = (act && 3 * g + 2 == j) ? 1.f : 0.f;
    int esum = 0;

#pragma unroll
    for (int s = 0; s < CHUNK; s++) {
        bool on = ((bits >> s) & 1u) != 0;
        float p = Psm[s * Tn + jc];
        float n0 = 0.f, n1 = 0.f, n2 = 0.f;
#pragma unroll
        for (int k = 0; k < Tn; k++) {
            int src = 3 * k + g;
            float a0 = __shfl_sync(0xffffffffu, v0, src);
            float a1 = __shfl_sync(0xffffffffu, v1, src);
            float a2 = __shfl_sync(0xffffffffu, v2, src);
            n0 = fmaf(a0, eT[k], n0);
            n1 = fmaf(a1, eT[k], n1);
            n2 = fmaf(a2, eT[k], n2);
        }
        bool take = on && act;
        v0 = take ? n0 * p : v0;
        v1 = take ? n1 * p : v1;
        v2 = take ? n2 * p : v2;

        if ((s & 3) == 3) {   // branchless exact power-of-2 renorm
            float lm = fmaxf(v0, fmaxf(v1, v2));
            unsigned mx = __reduce_max_sync(0xffffffffu, __float_as_uint(lm));
            int e = (int)(mx >> 23) - 127;
            float sc = __uint_as_float((unsigned)(127 - e) << 23);
            v0 *= sc; v1 *= sc; v2 *= sc;
            esum += e;
        }
    }

    if (act) {
        float* M = d_CM + (size_t)blk * 81;
        M[(3 * g + 0) * 9 + j] = v0;
        M[(3 * g + 1) * 9 + j] = v1;
        M[(3 * g + 2) * 9 + j] = v2;
    }
    if (lane == 0) d_CE[blk] = esum;

    // ---- per-batch combine: last chunk block of batch b ----
    __threadfence();
    unsigned done = 0;
    if (lane == 0) done = (atomicAdd(&d_bcnt[b], 1u) == NCHUNK - 1) ? 1u : 0u;
    done = __shfl_sync(0xffffffffu, done, 0);
    if (!done) return;
    __threadfence();

    // numerator partial sums (strided over t)
    float ps = 0.f;
    int cntm = 0;
    for (int t = lane; t < Sn; t += 32) {
        int lab2 = labels[b * Sn + t];
        bool valid = lab2 != -100;
        int lm = valid ? lab2 : 0;
        bool mb = (mask[b * Sn + t] != 0) && valid;
        if (mb) cntm++;
        if (mb && t >= 1) {
            int labp = labels[b * Sn + t - 1];
            int lmp = (labp != -100) ? labp : 0;
            ps += d_em[(size_t)(b * Sn + t) * Tn + lm] + __ldg(trans + lmp * Tn + lm);
        }
    }
#pragma unroll
    for (int o = 16; o > 0; o >>= 1) {
        ps += __shfl_xor_sync(0xffffffffu, ps, o);
        cntm += __shfl_xor_sync(0xffffffffu, cntm, o);
    }

    // stage all 32 chunk matrices into smem (MLP-saturated)
    const float* CMg = d_CM + (size_t)b * NCHUNK * 81;
    for (int i = lane; i < NCHUNK * 81; i += 32) CMsm[i] = CMg[i];
    int es2 = d_CE[b * NCHUNK + lane];          // NCHUNK == 32 lanes
    es2 = __reduce_add_sync(0xffffffffu, es2);
    __syncwarp();

    // alpha chain through 32 matrices (LDS reads, REDUX renorm)
    int jx = lane < 9 ? lane : 0;
    float a = (lane < 9)
        ? __expf(__ldg(startt + jx)) * d_ep[(size_t)(b * Sn) * Tn + jx] : 0.f;

#pragma unroll 4
    for (int c2 = 0; c2 < NCHUNK; c2++) {
        float Mi[9];
#pragma unroll
        for (int i = 0; i < 9; i++) Mi[i] = CMsm[c2 * 81 + i * 9 + jx];
        float s = 0.f;
#pragma unroll
        for (int i = 0; i < 9; i++)
            s = fmaf(__shfl_sync(0xffffffffu, a, i), Mi[i], s);
        a = (lane < 9) ? s : 0.f;

        unsigned mx = __reduce_max_sync(0xffffffffu, __float_as_uint(a));
        int e = (int)(mx >> 23) - 127;
        float sc = __uint_as_float((unsigned)(127 - e) << 23);
        a *= sc;
        es2 += e;
    }

    float v = (lane < 9) ? a * __expf(__ldg(endt + jx)) : 0.f;
#pragma unroll
    for (int o = 16; o > 0; o >>= 1)
        v += __shfl_xor_sync(0xffffffffu, v, o);

    if (lane == 0) {
        float denom = (float)es2 * 0.69314718055994530942f + __logf(v);
        int l0 = labels[b * Sn];
        if (l0 == -100) l0 = 0;
        float first = __ldg(startt + l0) + d_em[(size_t)(b * Sn) * Tn + l0];
        int last_idx = cntm - 1;
        int ll = labels[b * Sn + last_idx];
        if (ll == -100) ll = 0;
        float num = first + ps + __ldg(endt + ll);
        float nll = denom - num;

        d_bcnt[b] = 0;   // reset ticket for next graph replay

        atomicAdd(&d_sum, nll * (1.0f / (float)Bn));
        __threadfence();
        unsigned cdone = atomicAdd(&d_cnt, 1u);
        if (cdone == Bn - 1) {
            float tot = atomicAdd(&d_sum, 0.0f);
            out[0] = tot;
            atomicExch(&d_sum, 0.0f);
            atomicExch(&d_cnt, 0u);
        }
    }
}

// ============================================================
extern "C" void kernel_launch(void* const* d_in, const int* in_sizes, int n_in,
                              void* d_out, int out_size)
{
    const float* emb    = (const float*)d_in[0];
    const float* W      = (const float*)d_in[1];
    const float* bias   = (const float*)d_in[2];
    const float* startt = (const float*)d_in[3];
    const float* trans  = (const float*)d_in[4];
    const float* endt   = (const float*)d_in[5];
    const int*   labels = (const int*)d_in[6];
    const int*   mask   = (const int*)d_in[7];

    emis_kernel<<<512, 256>>>(emb, W, bias);
    chunk_kernel<<<Bn * NCHUNK, 32>>>(labels, mask, trans, startt, endt,
                                      (float*)d_out);
}

// round 5
// speedup vs baseline: 1.1790x; 1.0136x over previous
#include <cuda_runtime.h>
#include <math.h>

#define Bn 64
#define Sn 512
#define Hn 768
#define Tn 9
#define NCHUNK 32
#define CHUNK 16                         /* Sn / NCHUNK */
#define NCHTOT (Bn * NCHUNK)             /* 2048 chunks total */
#define CPB 12                           /* chunks per block (4 warps x 3) */
#define NBLK ((NCHTOT + CPB - 1) / CPB)  /* 171 */

// ---- static device scratch ----
__device__ float d_em[Bn * Sn * Tn];     // relu emissions
__device__ float d_ep[Bn * Sn * Tn];     // exp(relu emissions)
__device__ float d_CM[NCHTOT * 81];      // chunk transfer matrices (scaled 2^-CE)
__device__ int   d_CE[NCHTOT];           // chunk log2 scales
__device__ float d_sum;                  // final accumulator (zero-init)
__device__ unsigned d_cnt;               // batch ticket (zero-init)

// ============================================================
// Kernel A: emissions = relu(emb @ W^T + b); store em and exp(em).
// Warp = 8 rows x 4 k-lanes. Batched e-prefetch: 8 float4 LDGs
// in flight per warp (32 DRAM lines) to saturate HBM.
// ============================================================
__global__ __launch_bounds__(256) void emis_kernel(
    const float* __restrict__ emb,
    const float* __restrict__ W,
    const float* __restrict__ bias)
{
    int tid  = threadIdx.x;
    int lane = tid & 31;
    int warp = tid >> 5;
    int rsub = lane >> 2;          // row within warp (0..7)
    int q    = lane & 3;           // k-slice (0..3)
    int row  = blockIdx.x * 64 + warp * 8 + rsub;

    const float4* eg = (const float4*)emb + (size_t)row * (Hn / 4);
    const float4* Wg = (const float4*)W;

    float acc[Tn];
#pragma unroll
    for (int t = 0; t < Tn; t++) acc[t] = 0.f;

#pragma unroll 1
    for (int base = 0; base < 48; base += 8) {
        float4 eb[8];
#pragma unroll
        for (int u = 0; u < 8; u++)
            eb[u] = __ldg(eg + (q + 4 * (base + u)));
#pragma unroll
        for (int u = 0; u < 8; u++) {
            int k4 = q + 4 * (base + u);
            float4 e = eb[u];
#pragma unroll
            for (int t = 0; t < Tn; t++) {
                float4 w = __ldg(Wg + t * (Hn / 4) + k4);
                acc[t] = fmaf(e.x, w.x, acc[t]);
                acc[t] = fmaf(e.y, w.y, acc[t]);
                acc[t] = fmaf(e.z, w.z, acc[t]);
                acc[t] = fmaf(e.w, w.w, acc[t]);
            }
        }
    }

#pragma unroll
    for (int t = 0; t < Tn; t++) {
        acc[t] += __shfl_xor_sync(0xffffffffu, acc[t], 2);
        acc[t] += __shfl_xor_sync(0xffffffffu, acc[t], 1);
    }

    if (q == 0) {
        size_t b = (size_t)row * Tn;
#pragma unroll
        for (int t = 0; t < Tn; t++) {
            float v = acc[t] + __ldg(bias + t);
            v = v > 0.f ? v : 0.f;
            d_em[b + t] = v;
            d_ep[b + t] = __expf(v);
        }
    }
}

// ============================================================
// Kernel B: chunk transfer matrices, ROW-parallel (no shuffles).
// Lane = one matrix row: m[9] regs; eT (exp(trans), 81) in regs.
// Warp = 3 chunks (27 active lanes); block = 128 thr = 12 chunks.
// Renorm: per-row exact pow2 (bit tricks), chunk-common exponent
// aligned at the end through 9 smem ints per chunk.
// ============================================================
__global__ __launch_bounds__(128) void chunk_kernel(
    const int* __restrict__ labels,
    const int* __restrict__ mask,
    const float* __restrict__ trans)
{
    __shared__ float eTsm[81];
    __shared__ float Psm[CPB * CHUNK * Tn];   // 1728 floats
    __shared__ unsigned bitsm[CPB];
    __shared__ int tsm[CPB * Tn];

    int tid = threadIdx.x, w = tid >> 5, lane = tid & 31;

    if (tid < 81) eTsm[tid] = __expf(trans[tid]);

    // stage exp(emissions) for this block's 12 contiguous chunks
    int gbase = blockIdx.x * (CPB * CHUNK * Tn);
    for (int i = tid; i < CPB * CHUNK * Tn; i += 128) {
        int gi = gbase + i;
        Psm[i] = (gi < Bn * Sn * Tn) ? d_ep[gi] : 1.0f;
    }

    // per-chunk 16-bit active masks via ballot (2 chunks per warp per round)
#pragma unroll
    for (int r = 0; r < 2; r++) {
        int lc = r * 8 + 2 * w + (lane >> 4);
        int s = lane & 15;
        int cidx = blockIdx.x * CPB + lc;
        unsigned bit = 0;
        if (lc < CPB && cidx < NCHTOT) {
            int t = cidx * CHUNK + s;
            int lab = labels[t];
            int mk = mask[t];
            bit = (mk != 0 && lab != -100) ? 1u : 0u;
            if ((cidx & (NCHUNK - 1)) == 0 && s == 0) bit = 0;  // t==0 excluded
        }
        unsigned bal = __ballot_sync(0xffffffffu, bit);
        if ((lane == 0 || lane == 16) && lc < CPB)
            bitsm[lc] = (lane == 0) ? (bal & 0xFFFFu) : (bal >> 16);
    }
    __syncthreads();

    int u = lane < 27 ? lane / 9 : 0;
    int i = lane < 27 ? lane - 9 * u : 0;
    bool act = lane < 27;
    int lc = w * 3 + u;
    int cidx = blockIdx.x * CPB + lc;
    bool valid = act && (cidx < NCHTOT);

    float eTr[81];
#pragma unroll
    for (int x = 0; x < 81; x++) eTr[x] = eTsm[x];

    unsigned bits = bitsm[lc];
    const float* P = Psm + lc * (CHUNK * Tn);

    float m[9];
#pragma unroll
    for (int j = 0; j < 9; j++) m[j] = (j == i) ? 1.f : 0.f;
    int es = 0;

#pragma unroll 2
    for (int s = 0; s < CHUNK; s++) {
        bool take = ((bits >> s) & 1u) != 0;
        float a0 = 0.f, a1 = 0.f, a2 = 0.f, a3 = 0.f, a4 = 0.f;
        float a5 = 0.f, a6 = 0.f, a7 = 0.f, a8 = 0.f;
#pragma unroll
        for (int k = 0; k < 9; k++) {
            float mk = m[k];
            const float* e = &eTr[k * 9];
            a0 = fmaf(mk, e[0], a0); a1 = fmaf(mk, e[1], a1);
            a2 = fmaf(mk, e[2], a2); a3 = fmaf(mk, e[3], a3);
            a4 = fmaf(mk, e[4], a4); a5 = fmaf(mk, e[5], a5);
            a6 = fmaf(mk, e[6], a6); a7 = fmaf(mk, e[7], a7);
            a8 = fmaf(mk, e[8], a8);
        }
        float acc[9] = {a0, a1, a2, a3, a4, a5, a6, a7, a8};
#pragma unroll
        for (int j = 0; j < 9; j++) {
            float nv = acc[j] * P[s * Tn + j];
            m[j] = take ? nv : m[j];
        }
        if (s == 7) {   // per-row exact pow2 overflow renorm
            float rm = m[0];
#pragma unroll
            for (int j = 1; j < 9; j++) rm = fmaxf(rm, m[j]);
            int e = (int)(__float_as_uint(rm) >> 23) - 127;
            float sc = __uint_as_float((unsigned)(127 - e) << 23);
#pragma unroll
            for (int j = 0; j < 9; j++) m[j] *= sc;
            es += e;
        }
    }

    // align all rows of a chunk to a common exponent
    float rm = m[0];
#pragma unroll
    for (int j = 1; j < 9; j++) rm = fmaxf(rm, m[j]);
    int r_i = (int)(__float_as_uint(rm) >> 23) - 127;
    if (act) tsm[lc * Tn + i] = es + r_i;
    __syncwarp();
    int emax = tsm[lc * Tn];
#pragma unroll
    for (int k = 1; k < 9; k++) emax = max(emax, tsm[lc * Tn + k]);
    float sc2 = exp2f((float)(es - emax));   // stored = true * 2^-emax

    if (valid) {
        float* M = d_CM + (size_t)cidx * 81 + i * 9;
#pragma unroll
        for (int j = 0; j < 9; j++) M[j] = m[j] * sc2;
        if (i == 0) d_CE[cidx] = emax;
    }
}

// ============================================================
// Kernel C: per-batch combine + numerator; atomic mean finalize.
// One warp per batch; chunk matrices staged through smem.
// ============================================================
__global__ __launch_bounds__(32) void combine_kernel(
    const int* __restrict__ labels,
    const int* __restrict__ mask,
    const float* __restrict__ trans,
    const float* __restrict__ startt,
    const float* __restrict__ endt,
    float* __restrict__ out)
{
    __shared__ float CMsm[NCHUNK * 81];   // 10368 B
    int b = blockIdx.x;
    int lane = threadIdx.x;

    // stage all 32 chunk matrices (coalesced, MLP-saturated)
    const float* CMg = d_CM + (size_t)b * NCHUNK * 81;
    for (int i = lane; i < NCHUNK * 81; i += 32) CMsm[i] = CMg[i];
    int es2 = d_CE[b * NCHUNK + lane];
    es2 = __reduce_add_sync(0xffffffffu, es2);

    // numerator partial sums
    float ps = 0.f;
    int cntm = 0;
    for (int t = lane; t < Sn; t += 32) {
        int lab2 = labels[b * Sn + t];
        bool vld = lab2 != -100;
        int lm = vld ? lab2 : 0;
        bool mb = (mask[b * Sn + t] != 0) && vld;
        if (mb) cntm++;
        if (mb && t >= 1) {
            int labp = labels[b * Sn + t - 1];
            int lmp = (labp != -100) ? labp : 0;
            ps += d_em[(size_t)(b * Sn + t) * Tn + lm] + __ldg(trans + lmp * Tn + lm);
        }
    }
#pragma unroll
    for (int o = 16; o > 0; o >>= 1) {
        ps += __shfl_xor_sync(0xffffffffu, ps, o);
        cntm += __shfl_xor_sync(0xffffffffu, cntm, o);
    }
    __syncwarp();

    // alpha chain through 32 matrices (LDS + REDUX renorm)
    int jx = lane < 9 ? lane : 0;
    float a = (lane < 9)
        ? __expf(__ldg(startt + jx)) * d_ep[(size_t)(b * Sn) * Tn + jx] : 0.f;

#pragma unroll 4
    for (int c2 = 0; c2 < NCHUNK; c2++) {
        float Mi[9];
#pragma unroll
        for (int i = 0; i < 9; i++) Mi[i] = CMsm[c2 * 81 + i * 9 + jx];
        float s = 0.f;
#pragma unroll
        for (int i = 0; i < 9; i++)
            s = fmaf(__shfl_sync(0xffffffffu, a, i), Mi[i], s);
        a = (lane < 9) ? s : 0.f;

        unsigned mx = __reduce_max_sync(0xffffffffu, __float_as_uint(a));
        int e = (int)(mx >> 23) - 127;
        float sc = __uint_as_float((unsigned)(127 - e) << 23);
        a *= sc;
        es2 += e;
    }

    float v = (lane < 9) ? a * __expf(__ldg(endt + jx)) : 0.f;
#pragma unroll
    for (int o = 16; o > 0; o >>= 1)
        v += __shfl_xor_sync(0xffffffffu, v, o);

    if (lane == 0) {
        float denom = (float)es2 * 0.69314718055994530942f + __logf(v);
        int l0 = labels[b * Sn];
        if (l0 == -100) l0 = 0;
        float first = __ldg(startt + l0) + d_em[(size_t)(b * Sn) * Tn + l0];
        int ll = labels[b * Sn + (cntm - 1)];
        if (ll == -100) ll = 0;
        float num = first + ps + __ldg(endt + ll);
        float nll = denom - num;

        atomicAdd(&d_sum, nll * (1.0f / (float)Bn));
        __threadfence();
        unsigned cdone = atomicAdd(&d_cnt, 1u);
        if (cdone == Bn - 1) {
            float tot = atomicAdd(&d_sum, 0.0f);
            out[0] = tot;
            atomicExch(&d_sum, 0.0f);
            atomicExch(&d_cnt, 0u);
        }
    }
}

// ============================================================
extern "C" void kernel_launch(void* const* d_in, const int* in_sizes, int n_in,
                              void* d_out, int out_size)
{
    const float* emb    = (const float*)d_in[0];
    const float* W      = (const float*)d_in[1];
    const float* bias   = (const float*)d_in[2];
    const float* startt = (const float*)d_in[3];
    const float* trans  = (const float*)d_in[4];
    const float* endt   = (const float*)d_in[5];
    const int*   labels = (const int*)d_in[6];
    const int*   mask   = (const int*)d_in[7];

    emis_kernel<<<512, 256>>>(emb, W, bias);
    chunk_kernel<<<NBLK, 128>>>(labels, mask, trans);
    combine_kernel<<<Bn, 32>>>(labels, mask, trans, startt, endt, (float*)d_out);
}